// round 15
// baseline (speedup 1.0000x reference)
#include <cuda_runtime.h>

#define IMG 256
#define TW 64
#define TH 32

typedef unsigned long long u64;

// 50.3 MB combo scratch, L2-resident between the two kernels.
// Layout: [channel][row][plane][col] -> one row's 4 planes within 4KB.
__device__ __align__(16) float g_scr[48][IMG][4][IMG];

// ---- packed f32x2 helpers ----
__device__ __forceinline__ u64 pk2(float lo, float hi) {
    u64 r; asm("mov.b64 %0, {%1,%2};" : "=l"(r) : "f"(lo), "f"(hi)); return r;
}
__device__ __forceinline__ void upk2(float& lo, float& hi, u64 p) {
    asm("mov.b64 {%0,%1}, %2;" : "=f"(lo), "=f"(hi) : "l"(p));
}
__device__ __forceinline__ u64 f2fma(u64 a, u64 b, u64 c) {
    u64 d; asm("fma.rn.f32x2 %0,%1,%2,%3;" : "=l"(d) : "l"(a), "l"(b), "l"(c)); return d;
}
__device__ __forceinline__ u64 f2mul(u64 a, u64 b) {
    u64 d; asm("mul.rn.f32x2 %0,%1,%2;" : "=l"(d) : "l"(a), "l"(b)); return d;
}
__device__ __forceinline__ u64 f2add(u64 a, u64 b) {
    u64 d; asm("add.rn.f32x2 %0,%1,%2;" : "=l"(d) : "l"(a), "l"(b)); return d;
}
__device__ __forceinline__ float ex2f(float x) {
    float r; asm("ex2.approx.f32 %0, %1;" : "=f"(r) : "f"(x)); return r;
}
__device__ __forceinline__ float rcpf(float x) {
    float r; asm("rcp.approx.f32 %0, %1;" : "=f"(r) : "f"(x)); return r;
}
__device__ __forceinline__ int reflect(int v) {
    v = (v < 0) ? -v : v;
    return (v > IMG - 1) ? 2 * (IMG - 1) - v : v;
}

// ---- Kernel 1: build horizontal combo planes for the whole image ----
// thread = 4 consecutive cols of one row. Perfectly coalesced LDG.128/STG.128.
__global__ __launch_bounds__(256)
void combo_kernel(const float* __restrict__ x)
{
    const int g   = blockIdx.x * 256 + threadIdx.x;   // 0 .. 786431
    const int c4  = (g & 63) << 2;                    // 0,4,...,252
    const int row = (g >> 6) & 255;
    const int ch  = g >> 14;

    const float* xr = x + ((size_t)ch * IMG + row) * IMG;

    float v[12];                                      // x[c4-4 .. c4+7]
    if (c4 >= 4 && c4 <= 248) {
        const float4* s = (const float4*)(xr + c4 - 4);
        float4 f0 = s[0], f1 = s[1], f2 = s[2];
        v[0]=f0.x; v[1]=f0.y; v[2]=f0.z;  v[3]=f0.w;
        v[4]=f1.x; v[5]=f1.y; v[6]=f1.z;  v[7]=f1.w;
        v[8]=f2.x; v[9]=f2.y; v[10]=f2.z; v[11]=f2.w;
    } else {
        #pragma unroll
        for (int j = 0; j < 12; j++)
            v[j] = xr[reflect(c4 - 4 + j)];
    }

    // col c4+i: m=v[i+4], a=v[i+3]+v[i+5], b=v[i+2]+v[i+6], c=v[i+1]+v[i+7]
    float* d = &g_scr[ch][row][0][c4];
    *(float4*)(d)           = make_float4(v[4], v[5], v[6], v[7]);
    *(float4*)(d + IMG)     = make_float4(v[3]+v[5], v[4]+v[6], v[5]+v[7], v[6]+v[8]);
    *(float4*)(d + 2*IMG)   = make_float4(v[2]+v[6], v[3]+v[7], v[4]+v[8], v[5]+v[9]);
    *(float4*)(d + 3*IMG)   = make_float4(v[1]+v[7], v[2]+v[8], v[3]+v[9], v[4]+v[10]);
}

// ---- Kernel 2: apply adaptive weights. No smem, no barrier. ----
// thread = 2 cols x 4 rows, packed f32x2 math (R13 pass-2 body).
__global__ __launch_bounds__(256, 4)
void apply_kernel(const float* __restrict__ sigma,
                  float* __restrict__ out)
{
    const int ch = blockIdx.z;
    const int x0 = blockIdx.x * TW;
    const int y0 = blockIdx.y * TH;

    const float* sc = sigma + (size_t)ch * IMG * IMG;
    float*       oc = out   + (size_t)ch * IMG * IMG;

    const int tx  = threadIdx.x;
    const int ty  = threadIdx.y;
    const int c2  = tx << 1;                 // 0..62
    const int ly0 = ty << 2;                 // 0..28

    // Preload 4 sigma pairs
    const float* sp = sc + (y0 + ly0) * IMG + x0 + c2;
    u64 sg[4];
    sg[0] = *(const u64*)(sp);
    sg[1] = *(const u64*)(sp + IMG);
    sg[2] = *(const u64*)(sp + 2 * IMG);
    sg[3] = *(const u64*)(sp + 3 * IMG);

    // Exp chains (overlap with combo loads below via scheduling)
    const u64 NHL = pk2(-0.72134752f, -0.72134752f);   // -0.5*log2(e)
    u64 t[4], t4[4], t9[4];
    #pragma unroll
    for (int k = 0; k < 4; k++) {
        u64 z = f2mul(sg[k], sg[k]);
        z = f2mul(z, NHL);
        float zl, zh; upk2(zl, zh, z);
        t[k]  = pk2(ex2f(zl), ex2f(zh));
        u64 t2 = f2mul(t[k], t[k]);
        t4[k] = f2mul(t2, t2);
        t9[k] = f2mul(f2mul(t4[k], t4[k]), t[k]);
    }

    // Combo base for this channel/column (row stride = 4*IMG floats = 4KB)
    const float* sb = &g_scr[ch][0][0][x0 + c2];

    u64 acc[4];
    #pragma unroll
    for (int w = -3; w <= 6; w++) {
        int r = y0 + ly0 + w;
        r = (r < 0) ? -r : r;
        r = (r > IMG - 1) ? 2 * (IMG - 1) - r : r;   // vertical reflect
        const float* rp = sb + (size_t)r * (4 * IMG);
        const u64 qm_ = *(const u64*)(rp);
        const u64 qa_ = *(const u64*)(rp + IMG);
        const u64 qb_ = *(const u64*)(rp + 2 * IMG);
        const u64 qc_ = *(const u64*)(rp + 3 * IMG);
        #pragma unroll
        for (int k = 0; k < 4; k++) {
            const int d = (w > k) ? (w - k) : (k - w);
            if (d > 3) continue;
            u64 h = f2fma(t[k],  qa_, qm_);
            h     = f2fma(t4[k], qb_, h);
            h     = f2fma(t9[k], qc_, h);
            if (w == k - 3)     acc[k] = f2mul(t9[k], h);     // first contribution
            else if (d == 3)    acc[k] = f2fma(t9[k], h, acc[k]);
            else if (d == 2)    acc[k] = f2fma(t4[k], h, acc[k]);
            else if (d == 1)    acc[k] = f2fma(t[k],  h, acc[k]);
            else                acc[k] = f2add(acc[k], h);
        }
    }

    // Epilogue: normalize and store
    const u64 TWO2 = pk2(2.0f, 2.0f);
    const u64 ONE2 = pk2(1.0f, 1.0f);
    float* op = oc + (y0 + ly0) * IMG + x0 + c2;
    #pragma unroll
    for (int k = 0; k < 4; k++) {
        u64 S  = f2fma(TWO2, f2add(f2add(t[k], t4[k]), t9[k]), ONE2);
        u64 SS = f2mul(S, S);
        float sl, sh; upk2(sl, sh, SS);
        float al, ah; upk2(al, ah, acc[k]);
        *(u64*)(op + k * IMG) = pk2(al * rcpf(sl), ah * rcpf(sh));
    }
}

extern "C" void kernel_launch(void* const* d_in, const int* in_sizes, int n_in,
                              void* d_out, int out_size)
{
    const float* x     = (const float*)d_in[0];
    const float* sigma = (const float*)d_in[1];
    float*       out   = (float*)d_out;

    combo_kernel<<<48 * IMG * IMG / 4 / 256, 256>>>(x);          // 3072 blocks

    dim3 block(32, 8, 1);
    dim3 grid(IMG / TW, IMG / TH, 16 * 3);                       // 4 x 8 x 48
    apply_kernel<<<grid, block>>>(sigma, out);
}

// round 16
// speedup vs baseline: 1.2369x; 1.2369x over previous
#include <cuda_runtime.h>

#define IMG 256
#define TW 64
#define TH 32
#define PR (TH + 6)   // 38 quartet-plane rows

typedef unsigned long long u64;

// ---- packed f32x2 helpers (sm_103a FFMA2 path, PTX-only) ----
__device__ __forceinline__ u64 pk2(float lo, float hi) {
    u64 r; asm("mov.b64 %0, {%1,%2};" : "=l"(r) : "f"(lo), "f"(hi)); return r;
}
__device__ __forceinline__ void upk2(float& lo, float& hi, u64 p) {
    asm("mov.b64 {%0,%1}, %2;" : "=f"(lo), "=f"(hi) : "l"(p));
}
__device__ __forceinline__ u64 f2fma(u64 a, u64 b, u64 c) {
    u64 d; asm("fma.rn.f32x2 %0,%1,%2,%3;" : "=l"(d) : "l"(a), "l"(b), "l"(c)); return d;
}
__device__ __forceinline__ u64 f2mul(u64 a, u64 b) {
    u64 d; asm("mul.rn.f32x2 %0,%1,%2;" : "=l"(d) : "l"(a), "l"(b)); return d;
}
__device__ __forceinline__ u64 f2add(u64 a, u64 b) {
    u64 d; asm("add.rn.f32x2 %0,%1,%2;" : "=l"(d) : "l"(a), "l"(b)); return d;
}
__device__ __forceinline__ float ex2f(float x) {
    float r; asm("ex2.approx.f32 %0, %1;" : "=f"(r) : "f"(x)); return r;
}
__device__ __forceinline__ float rcpf(float x) {
    float r; asm("rcp.approx.f32 %0, %1;" : "=f"(r) : "f"(x)); return r;
}
__device__ __forceinline__ int reflect(int v) {
    v = (v < 0) ? -v : v;
    return (v > IMG - 1) ? 2 * (IMG - 1) - v : v;
}

__global__ __launch_bounds__(256, 4)
void AdaptiveGaussianFilter_66675072303489_kernel(
    const float* __restrict__ x,
    const float* __restrict__ sigma,
    float* __restrict__ out)
{
    // Planar quartet planes: m=w0, a=w-1+w+1, b=w-2+w+2, c=w-3+w+3 (38.9 KB)
    __shared__ __align__(16) float qm[PR][TW];
    __shared__ __align__(16) float qa[PR][TW];
    __shared__ __align__(16) float qb[PR][TW];
    __shared__ __align__(16) float qc[PR][TW];

    const int ch = blockIdx.z;
    const int x0 = blockIdx.x * TW;
    const int y0 = blockIdx.y * TH;

    const float* xc = x     + (size_t)ch * IMG * IMG;
    const float* sc = sigma + (size_t)ch * IMG * IMG;
    float*       oc = out   + (size_t)ch * IMG * IMG;

    const int tx  = threadIdx.x;
    const int ty  = threadIdx.y;
    const int tid = ty * 32 + tx;

    const int c2  = tx << 1;                 // column 0..62
    const int ly0 = ty << 2;                 // output row 0..28

    // ---- Issue ALL global loads first: sigma pairs + both main strips ----
    const float* sp = sc + (y0 + ly0) * IMG + x0 + c2;
    u64 sg[4];
    sg[0] = *(const u64*)(sp);
    sg[1] = *(const u64*)(sp + IMG);
    sg[2] = *(const u64*)(sp + 2 * IMG);
    sg[3] = *(const u64*)(sp + 3 * IMG);

    const bool interior = (blockIdx.x != 0) & (blockIdx.x != 3) &
                          (blockIdx.y != 0) & (blockIdx.y != 7);

    // Strip indices: s0 = tid, s1 = tid + 256, tail s2 = tid + 512 (tid < 96)
    const int r0 = tid >> 4,          c0 = (tid & 15) << 2;
    const int r1 = (tid + 256) >> 4,  c1 = ((tid + 256) & 15) << 2;

    float v0[12], v1[12];
    if (interior) {
        const float4* p0 = (const float4*)(xc + (y0 + r0 - 3) * IMG + (x0 + c0 - 4));
        const float4* p1 = (const float4*)(xc + (y0 + r1 - 3) * IMG + (x0 + c1 - 4));
        // issue all 6 LDG.128 back-to-back (max MLP)
        float4 a0 = p0[0], a1 = p0[1], a2 = p0[2];
        float4 b0 = p1[0], b1 = p1[1], b2 = p1[2];
        v0[0]=a0.x; v0[1]=a0.y; v0[2]=a0.z;  v0[3]=a0.w;
        v0[4]=a1.x; v0[5]=a1.y; v0[6]=a1.z;  v0[7]=a1.w;
        v0[8]=a2.x; v0[9]=a2.y; v0[10]=a2.z; v0[11]=a2.w;
        v1[0]=b0.x; v1[1]=b0.y; v1[2]=b0.z;  v1[3]=b0.w;
        v1[4]=b1.x; v1[5]=b1.y; v1[6]=b1.z;  v1[7]=b1.w;
        v1[8]=b2.x; v1[9]=b2.y; v1[10]=b2.z; v1[11]=b2.w;
    } else {
        const float* sr0 = xc + reflect(y0 + r0 - 3) * IMG;
        const float* sr1 = xc + reflect(y0 + r1 - 3) * IMG;
        #pragma unroll
        for (int j = 0; j < 12; j++) v0[j] = sr0[reflect(x0 + c0 - 4 + j)];
        #pragma unroll
        for (int j = 0; j < 12; j++) v1[j] = sr1[reflect(x0 + c1 - 4 + j)];
    }

    // ---- Exp chains now (MUFU runs while nothing depends on it) ----
    const u64 NHL = pk2(-0.72134752f, -0.72134752f);   // -0.5*log2(e)
    u64 t[4], t4[4], t9[4];
    #pragma unroll
    for (int k = 0; k < 4; k++) {
        u64 z = f2mul(sg[k], sg[k]);
        z = f2mul(z, NHL);
        float zl, zh; upk2(zl, zh, z);
        t[k]  = pk2(ex2f(zl), ex2f(zh));
        u64 t2 = f2mul(t[k], t[k]);
        t4[k] = f2mul(t2, t2);
        t9[k] = f2mul(f2mul(t4[k], t4[k]), t[k]);
    }

    // ---- Combos + stores for both main strips ----
    *(float4*)&qm[r0][c0] = make_float4(v0[4], v0[5], v0[6], v0[7]);
    *(float4*)&qa[r0][c0] = make_float4(v0[3]+v0[5], v0[4]+v0[6], v0[5]+v0[7], v0[6]+v0[8]);
    *(float4*)&qb[r0][c0] = make_float4(v0[2]+v0[6], v0[3]+v0[7], v0[4]+v0[8], v0[5]+v0[9]);
    *(float4*)&qc[r0][c0] = make_float4(v0[1]+v0[7], v0[2]+v0[8], v0[3]+v0[9], v0[4]+v0[10]);

    *(float4*)&qm[r1][c1] = make_float4(v1[4], v1[5], v1[6], v1[7]);
    *(float4*)&qa[r1][c1] = make_float4(v1[3]+v1[5], v1[4]+v1[6], v1[5]+v1[7], v1[6]+v1[8]);
    *(float4*)&qb[r1][c1] = make_float4(v1[2]+v1[6], v1[3]+v1[7], v1[4]+v1[8], v1[5]+v1[9]);
    *(float4*)&qc[r1][c1] = make_float4(v1[1]+v1[7], v1[2]+v1[8], v1[3]+v1[9], v1[4]+v1[10]);

    // ---- Tail strip (96 threads): rows 32..37 ----
    if (tid < PR * 16 - 512) {
        const int r2 = (tid + 512) >> 4, c2s = ((tid + 512) & 15) << 2;
        float v[12];
        if (interior) {
            const float4* p2 = (const float4*)(xc + (y0 + r2 - 3) * IMG + (x0 + c2s - 4));
            float4 f0 = p2[0], f1 = p2[1], f2 = p2[2];
            v[0]=f0.x; v[1]=f0.y; v[2]=f0.z;  v[3]=f0.w;
            v[4]=f1.x; v[5]=f1.y; v[6]=f1.z;  v[7]=f1.w;
            v[8]=f2.x; v[9]=f2.y; v[10]=f2.z; v[11]=f2.w;
        } else {
            const float* srow = xc + reflect(y0 + r2 - 3) * IMG;
            #pragma unroll
            for (int j = 0; j < 12; j++) v[j] = srow[reflect(x0 + c2s - 4 + j)];
        }
        *(float4*)&qm[r2][c2s] = make_float4(v[4], v[5], v[6], v[7]);
        *(float4*)&qa[r2][c2s] = make_float4(v[3]+v[5], v[4]+v[6], v[5]+v[7], v[6]+v[8]);
        *(float4*)&qb[r2][c2s] = make_float4(v[2]+v[6], v[3]+v[7], v[4]+v[8], v[5]+v[9]);
        *(float4*)&qc[r2][c2s] = make_float4(v[1]+v[7], v[2]+v[8], v[3]+v[9], v[4]+v[10]);
    }
    __syncthreads();

    // ---- Pass 2: stream 10 window rows; 4 packed accumulators ----
    u64 acc[4];
    #pragma unroll
    for (int w = -3; w <= 6; w++) {
        const int prow = ly0 + w + 3;        // 0..37
        const u64 qm_ = *(const u64*)&qm[prow][c2];
        const u64 qa_ = *(const u64*)&qa[prow][c2];
        const u64 qb_ = *(const u64*)&qb[prow][c2];
        const u64 qc_ = *(const u64*)&qc[prow][c2];
        #pragma unroll
        for (int k = 0; k < 4; k++) {
            const int d = (w > k) ? (w - k) : (k - w);
            if (d > 3) continue;
            u64 h = f2fma(t[k],  qa_, qm_);
            h     = f2fma(t4[k], qb_, h);
            h     = f2fma(t9[k], qc_, h);
            if (w == k - 3)     acc[k] = f2mul(t9[k], h);     // first contribution
            else if (d == 3)    acc[k] = f2fma(t9[k], h, acc[k]);
            else if (d == 2)    acc[k] = f2fma(t4[k], h, acc[k]);
            else if (d == 1)    acc[k] = f2fma(t[k],  h, acc[k]);
            else                acc[k] = f2add(acc[k], h);
        }
    }

    // ---- Epilogue: normalize and store ----
    const u64 TWO2 = pk2(2.0f, 2.0f);
    const u64 ONE2 = pk2(1.0f, 1.0f);
    float* op = oc + (y0 + ly0) * IMG + x0 + c2;
    #pragma unroll
    for (int k = 0; k < 4; k++) {
        u64 S  = f2fma(TWO2, f2add(f2add(t[k], t4[k]), t9[k]), ONE2);
        u64 SS = f2mul(S, S);
        float sl, sh; upk2(sl, sh, SS);
        float al, ah; upk2(al, ah, acc[k]);
        *(u64*)(op + k * IMG) = pk2(al * rcpf(sl), ah * rcpf(sh));
    }
}

extern "C" void kernel_launch(void* const* d_in, const int* in_sizes, int n_in,
                              void* d_out, int out_size)
{
    const float* x     = (const float*)d_in[0];
    const float* sigma = (const float*)d_in[1];
    float*       out   = (float*)d_out;

    dim3 block(32, 8, 1);
    dim3 grid(IMG / TW, IMG / TH, 16 * 3);   // 4 x 8 x 48 = 1536
    AdaptiveGaussianFilter_66675072303489_kernel<<<grid, block>>>(x, sigma, out);
}

// round 17
// speedup vs baseline: 1.2557x; 1.0152x over previous
#include <cuda_runtime.h>

#define IMG 256
#define TW 64
#define TH 32
#define PR (TH + 6)   // 38 quartet-plane rows

typedef unsigned long long u64;

// ---- packed f32x2 helpers (sm_103a FFMA2 path, PTX-only) ----
__device__ __forceinline__ u64 pk2(float lo, float hi) {
    u64 r; asm("mov.b64 %0, {%1,%2};" : "=l"(r) : "f"(lo), "f"(hi)); return r;
}
__device__ __forceinline__ void upk2(float& lo, float& hi, u64 p) {
    asm("mov.b64 {%0,%1}, %2;" : "=f"(lo), "=f"(hi) : "l"(p));
}
__device__ __forceinline__ u64 f2fma(u64 a, u64 b, u64 c) {
    u64 d; asm("fma.rn.f32x2 %0,%1,%2,%3;" : "=l"(d) : "l"(a), "l"(b), "l"(c)); return d;
}
__device__ __forceinline__ u64 f2mul(u64 a, u64 b) {
    u64 d; asm("mul.rn.f32x2 %0,%1,%2;" : "=l"(d) : "l"(a), "l"(b)); return d;
}
__device__ __forceinline__ u64 f2add(u64 a, u64 b) {
    u64 d; asm("add.rn.f32x2 %0,%1,%2;" : "=l"(d) : "l"(a), "l"(b)); return d;
}
__device__ __forceinline__ float ex2f(float x) {
    float r; asm("ex2.approx.f32 %0, %1;" : "=f"(r) : "f"(x)); return r;
}
__device__ __forceinline__ float rcpf(float x) {
    float r; asm("rcp.approx.f32 %0, %1;" : "=f"(r) : "f"(x)); return r;
}
__device__ __forceinline__ int reflect(int v) {
    v = (v < 0) ? -v : v;
    return (v > IMG - 1) ? 2 * (IMG - 1) - v : v;
}

// Load one 12-float strip window from a (row-reflected) row pointer.
// safe => three aligned LDG.128; else scalar column-reflected loads.
__device__ __forceinline__ void load_strip(const float* __restrict__ rowp,
                                           int gx0, bool safe, float* v)
{
    if (safe) {
        const float4* s = (const float4*)(rowp + gx0);
        float4 f0 = s[0], f1 = s[1], f2 = s[2];
        v[0]=f0.x; v[1]=f0.y; v[2]=f0.z;  v[3]=f0.w;
        v[4]=f1.x; v[5]=f1.y; v[6]=f1.z;  v[7]=f1.w;
        v[8]=f2.x; v[9]=f2.y; v[10]=f2.z; v[11]=f2.w;
    } else {
        #pragma unroll
        for (int j = 0; j < 12; j++)
            v[j] = rowp[reflect(gx0 + j)];
    }
}

__global__ __launch_bounds__(256, 4)
void AdaptiveGaussianFilter_66675072303489_kernel(
    const float* __restrict__ x,
    const float* __restrict__ sigma,
    float* __restrict__ out)
{
    // Planar quartet planes: m=w0, a=w-1+w+1, b=w-2+w+2, c=w-3+w+3 (38.9 KB)
    __shared__ __align__(16) float qm[PR][TW];
    __shared__ __align__(16) float qa[PR][TW];
    __shared__ __align__(16) float qb[PR][TW];
    __shared__ __align__(16) float qc[PR][TW];

    const int ch = blockIdx.z;
    const int x0 = blockIdx.x * TW;
    const int y0 = blockIdx.y * TH;

    const float* xc = x     + (size_t)ch * IMG * IMG;
    const float* sc = sigma + (size_t)ch * IMG * IMG;
    float*       oc = out   + (size_t)ch * IMG * IMG;

    const int tx  = threadIdx.x;
    const int ty  = threadIdx.y;
    const int tid = ty * 32 + tx;

    const int c2  = tx << 1;                 // column 0..62
    const int ly0 = ty << 2;                 // output row 0..28

    // ---- Issue ALL global loads first: sigma pairs + both main strips ----
    const float* sp = sc + (y0 + ly0) * IMG + x0 + c2;
    u64 sg[4];
    sg[0] = *(const u64*)(sp);
    sg[1] = *(const u64*)(sp + IMG);
    sg[2] = *(const u64*)(sp + 2 * IMG);
    sg[3] = *(const u64*)(sp + 3 * IMG);

    // Strip indices: s0 = tid, s1 = tid + 256, tail s2 = tid + 512 (tid < 96)
    const int r0 = tid >> 4,          c0 = (tid & 15) << 2;
    const int r1 = (tid + 256) >> 4,  c1 = ((tid + 256) & 15) << 2;

    // Row pointers: row-reflect is free (pointer only). Column safety per strip.
    const float* rp0 = xc + reflect(y0 + r0 - 3) * IMG;
    const float* rp1 = xc + reflect(y0 + r1 - 3) * IMG;
    const bool safe0 = (x0 + c0 >= 4) & (x0 + c0 <= 248);
    const bool safe1 = (x0 + c1 >= 4) & (x0 + c1 <= 248);

    float v0[12], v1[12];
    load_strip(rp0, x0 + c0 - 4, safe0, v0);
    load_strip(rp1, x0 + c1 - 4, safe1, v1);

    // ---- Exp chains now (MUFU runs while loads fly) ----
    const u64 NHL = pk2(-0.72134752f, -0.72134752f);   // -0.5*log2(e)
    u64 t[4], t4[4], t9[4];
    #pragma unroll
    for (int k = 0; k < 4; k++) {
        u64 z = f2mul(sg[k], sg[k]);
        z = f2mul(z, NHL);
        float zl, zh; upk2(zl, zh, z);
        t[k]  = pk2(ex2f(zl), ex2f(zh));
        u64 t2 = f2mul(t[k], t[k]);
        t4[k] = f2mul(t2, t2);
        t9[k] = f2mul(f2mul(t4[k], t4[k]), t[k]);
    }

    // ---- Combos + stores for both main strips ----
    *(float4*)&qm[r0][c0] = make_float4(v0[4], v0[5], v0[6], v0[7]);
    *(float4*)&qa[r0][c0] = make_float4(v0[3]+v0[5], v0[4]+v0[6], v0[5]+v0[7], v0[6]+v0[8]);
    *(float4*)&qb[r0][c0] = make_float4(v0[2]+v0[6], v0[3]+v0[7], v0[4]+v0[8], v0[5]+v0[9]);
    *(float4*)&qc[r0][c0] = make_float4(v0[1]+v0[7], v0[2]+v0[8], v0[3]+v0[9], v0[4]+v0[10]);

    *(float4*)&qm[r1][c1] = make_float4(v1[4], v1[5], v1[6], v1[7]);
    *(float4*)&qa[r1][c1] = make_float4(v1[3]+v1[5], v1[4]+v1[6], v1[5]+v1[7], v1[6]+v1[8]);
    *(float4*)&qb[r1][c1] = make_float4(v1[2]+v1[6], v1[3]+v1[7], v1[4]+v1[8], v1[5]+v1[9]);
    *(float4*)&qc[r1][c1] = make_float4(v1[1]+v1[7], v1[2]+v1[8], v1[3]+v1[9], v1[4]+v1[10]);

    // ---- Tail strip (96 threads): rows 32..37 ----
    if (tid < PR * 16 - 512) {
        const int r2 = (tid + 512) >> 4, c2s = ((tid + 512) & 15) << 2;
        const float* rp2 = xc + reflect(y0 + r2 - 3) * IMG;
        const bool safe2 = (x0 + c2s >= 4) & (x0 + c2s <= 248);
        float v[12];
        load_strip(rp2, x0 + c2s - 4, safe2, v);
        *(float4*)&qm[r2][c2s] = make_float4(v[4], v[5], v[6], v[7]);
        *(float4*)&qa[r2][c2s] = make_float4(v[3]+v[5], v[4]+v[6], v[5]+v[7], v[6]+v[8]);
        *(float4*)&qb[r2][c2s] = make_float4(v[2]+v[6], v[3]+v[7], v[4]+v[8], v[5]+v[9]);
        *(float4*)&qc[r2][c2s] = make_float4(v[1]+v[7], v[2]+v[8], v[3]+v[9], v[4]+v[10]);
    }
    __syncthreads();

    // ---- Pass 2: stream 10 window rows; 4 packed accumulators ----
    u64 acc[4];
    #pragma unroll
    for (int w = -3; w <= 6; w++) {
        const int prow = ly0 + w + 3;        // 0..37
        const u64 qm_ = *(const u64*)&qm[prow][c2];
        const u64 qa_ = *(const u64*)&qa[prow][c2];
        const u64 qb_ = *(const u64*)&qb[prow][c2];
        const u64 qc_ = *(const u64*)&qc[prow][c2];
        #pragma unroll
        for (int k = 0; k < 4; k++) {
            const int d = (w > k) ? (w - k) : (k - w);
            if (d > 3) continue;
            u64 h = f2fma(t[k],  qa_, qm_);
            h     = f2fma(t4[k], qb_, h);
            h     = f2fma(t9[k], qc_, h);
            if (w == k - 3)     acc[k] = f2mul(t9[k], h);     // first contribution
            else if (d == 3)    acc[k] = f2fma(t9[k], h, acc[k]);
            else if (d == 2)    acc[k] = f2fma(t4[k], h, acc[k]);
            else if (d == 1)    acc[k] = f2fma(t[k],  h, acc[k]);
            else                acc[k] = f2add(acc[k], h);
        }
    }

    // ---- Epilogue: normalize and store ----
    const u64 TWO2 = pk2(2.0f, 2.0f);
    const u64 ONE2 = pk2(1.0f, 1.0f);
    float* op = oc + (y0 + ly0) * IMG + x0 + c2;
    #pragma unroll
    for (int k = 0; k < 4; k++) {
        u64 S  = f2fma(TWO2, f2add(f2add(t[k], t4[k]), t9[k]), ONE2);
        u64 SS = f2mul(S, S);
        float sl, sh; upk2(sl, sh, SS);
        float al, ah; upk2(al, ah, acc[k]);
        *(u64*)(op + k * IMG) = pk2(al * rcpf(sl), ah * rcpf(sh));
    }
}

extern "C" void kernel_launch(void* const* d_in, const int* in_sizes, int n_in,
                              void* d_out, int out_size)
{
    const float* x     = (const float*)d_in[0];
    const float* sigma = (const float*)d_in[1];
    float*       out   = (float*)d_out;

    dim3 block(32, 8, 1);
    dim3 grid(IMG / TW, IMG / TH, 16 * 3);   // 4 x 8 x 48 = 1536
    AdaptiveGaussianFilter_66675072303489_kernel<<<grid, block>>>(x, sigma, out);
}